// round 1
// baseline (speedup 1.0000x reference)
#include <cuda_runtime.h>
#include <math.h>

// ---------------- problem constants ----------------
#define B_ 4
#define T_ 1024
#define D_ 1024
#define H_ 16
#define S_ 64
#define HID_ 3072
#define NTOK (B_*T_)            // 4096

// ---------------- device scratch (static, allowed) ----------------
__device__ float g_qwq[D_*D_];
__device__ float g_qwk[D_*D_];
__device__ float g_qwv[D_*D_];
__device__ float g_qwo[D_*D_];
__device__ float g_qsu[S_*S_];
__device__ float g_qsv[S_*S_];
__device__ float g_fwq[D_*D_];          // blockdiag(su_q) @ wq_q
__device__ float g_fwk[D_*D_];          // blockdiag(sv_q) @ wk_q
__device__ float g_qup[HID_*D_];
__device__ float g_qdn[D_*HID_];
__device__ float g_xn[NTOK*D_];
__device__ float g_Q[NTOK*D_];
__device__ float g_K[NTOK*D_];
__device__ float g_V[NTOK*D_];
__device__ float g_ao[NTOK*D_];
__device__ float g_h[NTOK*HID_];
__device__ float g_sc[(size_t)B_*H_*T_*T_];   // 256 MB score/attn buffer
__device__ unsigned g_maxabs[8];

// ---------------- small helpers ----------------
__device__ __forceinline__ float2 block_reduce2(float a, float b) {
    // blockDim.x up to 256 (multiple of 32)
    #pragma unroll
    for (int o = 16; o; o >>= 1) {
        a += __shfl_xor_sync(0xffffffffu, a, o);
        b += __shfl_xor_sync(0xffffffffu, b, o);
    }
    __shared__ float sa[8], sb[8];
    int w = threadIdx.x >> 5, l = threadIdx.x & 31;
    int nw = (blockDim.x + 31) >> 5;
    if (l == 0) { sa[w] = a; sb[w] = b; }
    __syncthreads();
    if (w == 0) {
        a = (l < nw) ? sa[l] : 0.f;
        b = (l < nw) ? sb[l] : 0.f;
        #pragma unroll
        for (int o = 4; o; o >>= 1) {
            a += __shfl_xor_sync(0xffffffffu, a, o);
            b += __shfl_xor_sync(0xffffffffu, b, o);
        }
        if (l == 0) { sa[0] = a; sb[0] = b; }
    }
    __syncthreads();
    return make_float2(sa[0], sb[0]);
}

// ---------------- quantization ----------------
__global__ void reset_k() {
    if (threadIdx.x < 8) g_maxabs[threadIdx.x] = 0u;
}

__global__ __launch_bounds__(256) void absmax_k(const float* __restrict__ w, int n, int slot) {
    float m = 0.f;
    for (int i = blockIdx.x * blockDim.x + threadIdx.x; i < n; i += gridDim.x * blockDim.x)
        m = fmaxf(m, fabsf(w[i]));
    #pragma unroll
    for (int o = 16; o; o >>= 1) m = fmaxf(m, __shfl_xor_sync(0xffffffffu, m, o));
    __shared__ float sm[8];
    if ((threadIdx.x & 31) == 0) sm[threadIdx.x >> 5] = m;
    __syncthreads();
    if (threadIdx.x < 8) {
        m = sm[threadIdx.x];
        #pragma unroll
        for (int o = 4; o; o >>= 1) m = fmaxf(m, __shfl_xor_sync(0xffu, m, o));
        if (threadIdx.x == 0) atomicMax(&g_maxabs[slot], __float_as_uint(m));
    }
}

__global__ __launch_bounds__(256) void quant_k(const float* __restrict__ w, float* __restrict__ out,
                                               int n, int slot) {
    float scale = __uint_as_float(g_maxabs[slot]) / 31.0f + 1e-8f;
    int i = blockIdx.x * blockDim.x + threadIdx.x;
    if (i < n) {
        float q = rintf(w[i] / scale);          // round-half-even like jnp.round
        q = fminf(fmaxf(q, -31.f), 31.f);
        out[i] = q * scale;
    }
}

// fw[h*64+s][k] = sum_j su[s][j] * w[h*64+j][k]   (k-block of 128 per blockIdx.x, head per blockIdx.y)
__global__ __launch_bounds__(256) void fuse_stalk_k(const float* __restrict__ su,
                                                    const float* __restrict__ w,
                                                    float* __restrict__ fw) {
    __shared__ float Ws[64][128];   // 32 KB
    __shared__ float Ss[64][64];    // 16 KB
    int h = blockIdx.y;
    int k0 = blockIdx.x * 128;
    int tid = threadIdx.x;
    // load W tile: rows h*64+j, cols k0..k0+127
    #pragma unroll
    for (int it = 0; it < 8; ++it) {
        int chunk = tid + it * 256;                 // 2048 float4 total
        int r = chunk >> 5, c4 = (chunk & 31) * 4;
        float4 v = *(const float4*)(w + (size_t)(h * 64 + r) * D_ + k0 + c4);
        *(float4*)&Ws[r][c4] = v;
    }
    // load su tile
    #pragma unroll
    for (int it = 0; it < 4; ++it) {
        int chunk = tid + it * 256;                 // 1024 float4
        int r = chunk >> 4, c4 = (chunk & 15) * 4;
        float4 v = *(const float4*)(su + (size_t)r * 64 + c4);
        *(float4*)&Ss[r][c4] = v;
    }
    __syncthreads();
    #pragma unroll 4
    for (int it = 0; it < 32; ++it) {
        int oidx = tid + it * 256;
        int s = oidx >> 7, kk = oidx & 127;
        float acc = 0.f;
        #pragma unroll
        for (int j = 0; j < 64; ++j) acc += Ss[s][j] * Ws[j][kk];
        fw[(size_t)(h * 64 + s) * D_ + k0 + kk] = acc;
    }
}

// ---------------- layernorm over D=1024 ----------------
__global__ __launch_bounds__(256) void ln_k(const float* __restrict__ x, const float* __restrict__ g,
                                            const float* __restrict__ bb, float* __restrict__ out) {
    int row = blockIdx.x;
    const float* xr = x + (size_t)row * D_;
    int c = threadIdx.x * 4;
    float4 v = *(const float4*)(xr + c);
    float s = v.x + v.y + v.z + v.w;
    float sq = v.x * v.x + v.y * v.y + v.z * v.z + v.w * v.w;
    float2 r = block_reduce2(s, sq);
    float mu = r.x * (1.0f / D_);
    float var = r.y * (1.0f / D_) - mu * mu;
    float inv = rsqrtf(var + 1e-5f);
    float4 gg = *(const float4*)(g + c);
    float4 bv = *(const float4*)(bb + c);
    float4 o;
    o.x = (v.x - mu) * inv * gg.x + bv.x;
    o.y = (v.y - mu) * inv * gg.y + bv.y;
    o.z = (v.z - mu) * inv * gg.z + bv.z;
    o.w = (v.w - mu) * inv * gg.w + bv.w;
    *(float4*)(out + (size_t)row * D_ + c) = o;
}

// ---------------- generic SGEMM: C[M,N] = A[M,K] @ Bw[N,K]^T (+Res) ----------------
__global__ __launch_bounds__(256) void sgemm_nt(const float* __restrict__ A,
                                                const float* __restrict__ Bw,
                                                const float* __restrict__ Res,
                                                float* __restrict__ C,
                                                int M, int N, int K) {
    __shared__ float As[8][132];
    __shared__ float Bs[8][132];
    int m0 = blockIdx.y * 128, n0 = blockIdx.x * 128;
    int tid = threadIdx.x;
    int lr = tid >> 1, lc = (tid & 1) * 4;
    const float* Ap = A + (size_t)(m0 + lr) * K + lc;
    const float* Bp = Bw + (size_t)(n0 + lr) * K + lc;
    int tr = (tid >> 4) * 8, tc = (tid & 15) * 8;
    float acc[8][8];
    #pragma unroll
    for (int i = 0; i < 8; ++i)
        #pragma unroll
        for (int j = 0; j < 8; ++j) acc[i][j] = 0.f;

    for (int k0 = 0; k0 < K; k0 += 8) {
        float4 av = *(const float4*)(Ap + k0);
        float4 bv = *(const float4*)(Bp + k0);
        As[lc + 0][lr] = av.x; As[lc + 1][lr] = av.y; As[lc + 2][lr] = av.z; As[lc + 3][lr] = av.w;
        Bs[lc + 0][lr] = bv.x; Bs[lc + 1][lr] = bv.y; Bs[lc + 2][lr] = bv.z; Bs[lc + 3][lr] = bv.w;
        __syncthreads();
        #pragma unroll
        for (int k = 0; k < 8; ++k) {
            float4 a0 = *(const float4*)&As[k][tr];
            float4 a1 = *(const float4*)&As[k][tr + 4];
            float4 b0 = *(const float4*)&Bs[k][tc];
            float4 b1 = *(const float4*)&Bs[k][tc + 4];
            float ar[8] = {a0.x, a0.y, a0.z, a0.w, a1.x, a1.y, a1.z, a1.w};
            float br[8] = {b0.x, b0.y, b0.z, b0.w, b1.x, b1.y, b1.z, b1.w};
            #pragma unroll
            for (int i = 0; i < 8; ++i)
                #pragma unroll
                for (int j = 0; j < 8; ++j) acc[i][j] += ar[i] * br[j];
        }
        __syncthreads();
    }
    #pragma unroll
    for (int i = 0; i < 8; ++i) {
        int m = m0 + tr + i;
        float* crow = C + (size_t)m * N + n0 + tc;
        if (Res) {
            const float* rrow = Res + (size_t)m * N + n0 + tc;
            #pragma unroll
            for (int j = 0; j < 8; ++j) crow[j] = acc[i][j] + rrow[j];
        } else {
            #pragma unroll
            for (int j = 0; j < 8; ++j) crow[j] = acc[i][j];
        }
    }
}

// ---------------- scores: per (b,h) 64x64 tiles, Qs@Ks^T * 0.125 + p_scale*bias ----------------
__global__ __launch_bounds__(256) void scores_k(const float* __restrict__ p_scale) {
    int ut = blockIdx.x, tt = blockIdx.y, bh = blockIdx.z;
    if (ut > tt) return;                         // strictly above diagonal: never read
    int b = bh >> 4, h = bh & 15;
    __shared__ float Qs[64][67];
    __shared__ float Ks[64][67];
    int tid = threadIdx.x;
    int lr = tid >> 2, lc = (tid & 3) * 16;
    {
        const float* qb = g_Q + (size_t)(b * T_ + tt * 64 + lr) * D_ + h * 64 + lc;
        const float* kb = g_K + (size_t)(b * T_ + ut * 64 + lr) * D_ + h * 64 + lc;
        #pragma unroll
        for (int i = 0; i < 4; ++i) {
            float4 qv = *(const float4*)(qb + i * 4);
            float4 kv = *(const float4*)(kb + i * 4);
            Qs[lr][lc + i * 4 + 0] = qv.x; Qs[lr][lc + i * 4 + 1] = qv.y;
            Qs[lr][lc + i * 4 + 2] = qv.z; Qs[lr][lc + i * 4 + 3] = qv.w;
            Ks[lr][lc + i * 4 + 0] = kv.x; Ks[lr][lc + i * 4 + 1] = kv.y;
            Ks[lr][lc + i * 4 + 2] = kv.z; Ks[lr][lc + i * 4 + 3] = kv.w;
        }
    }
    __syncthreads();
    int tr = (tid >> 4) * 4, tc = (tid & 15) * 4;
    float acc[4][4] = {};
    #pragma unroll 16
    for (int k = 0; k < 64; ++k) {
        float qr[4], kr[4];
        #pragma unroll
        for (int i = 0; i < 4; ++i) qr[i] = Qs[tr + i][k];
        #pragma unroll
        for (int j = 0; j < 4; ++j) kr[j] = Ks[tc + j][k];
        #pragma unroll
        for (int i = 0; i < 4; ++i)
            #pragma unroll
            for (int j = 0; j < 4; ++j) acc[i][j] += qr[i] * kr[j];
    }
    float ps = p_scale[0];
    #pragma unroll
    for (int i = 0; i < 4; ++i) {
        int t = tt * 64 + tr + i;
        float* row = g_sc + ((size_t)bh * T_ + t) * T_;
        #pragma unroll
        for (int j = 0; j < 4; ++j) {
            int u = ut * 64 + tc + j;
            int d = t - u; d = d < 0 ? -d : d;
            float bias;
            if (d == 0) bias = 1.0f;
            else {
                int vp = __ffs(d) - 1;        // 2-adic valuation
                vp = vp > 16 ? 16 : vp;
                bias = (float)vp * (1.0f / 16.0f);
            }
            row[u] = acc[i][j] * 0.125f + ps * bias;
        }
    }
}

// ---------------- causal softmax per row (zero-fills to 64-boundary) ----------------
__global__ __launch_bounds__(128) void softmax_k() {
    int t = blockIdx.x, bh = blockIdx.y;
    float* row = g_sc + ((size_t)bh * T_ + t) * T_;
    int tid = threadIdx.x;
    float v[8];
    float mx = -INFINITY;
    #pragma unroll
    for (int i = 0; i < 8; ++i) {
        int u = tid + i * 128;
        v[i] = (u <= t) ? row[u] : -INFINITY;
        mx = fmaxf(mx, v[i]);
    }
    __shared__ float red[4];
    #pragma unroll
    for (int o = 16; o; o >>= 1) mx = fmaxf(mx, __shfl_xor_sync(0xffffffffu, mx, o));
    if ((tid & 31) == 0) red[tid >> 5] = mx;
    __syncthreads();
    mx = fmaxf(fmaxf(red[0], red[1]), fmaxf(red[2], red[3]));
    float sum = 0.f;
    #pragma unroll
    for (int i = 0; i < 8; ++i) {
        float e = expf(v[i] - mx);        // expf(-inf)=0
        v[i] = e;
        sum += e;
    }
    __shared__ float red2[4];
    #pragma unroll
    for (int o = 16; o; o >>= 1) sum += __shfl_xor_sync(0xffffffffu, sum, o);
    if ((tid & 31) == 0) red2[tid >> 5] = sum;
    __syncthreads();
    sum = red2[0] + red2[1] + red2[2] + red2[3];
    float inv = 1.0f / sum;
    int fillEnd = ((t >> 6) + 1) << 6;
    #pragma unroll
    for (int i = 0; i < 8; ++i) {
        int u = tid + i * 128;
        if (u <= t) row[u] = v[i] * inv;
        else if (u < fillEnd) row[u] = 0.f;
    }
}

// ---------------- out = attn @ V, per (b,h), causal k-range ----------------
__global__ __launch_bounds__(256) void av_k() {
    int tt = blockIdx.x, bh = blockIdx.y;
    int b = bh >> 4, h = bh & 15;
    __shared__ float As[64][68];   // attn[t][u]
    __shared__ float Bs[64][68];   // V[u][s]
    int tid = threadIdx.x;
    int lr = tid >> 2, lc = (tid & 3) * 16;
    int tr = (tid >> 4) * 4, tc = (tid & 15) * 4;
    float acc[4][4] = {};
    const float* arow = g_sc + ((size_t)bh * T_ + tt * 64 + lr) * T_ + lc;
    for (int u0 = 0; u0 <= tt * 64; u0 += 64) {
        #pragma unroll
        for (int i = 0; i < 4; ++i)
            *(float4*)&As[lr][lc + i * 4] = *(const float4*)(arow + u0 + i * 4);
        const float* vrow = g_V + (size_t)(b * T_ + u0 + lr) * D_ + h * 64 + lc;
        #pragma unroll
        for (int i = 0; i < 4; ++i)
            *(float4*)&Bs[lr][lc + i * 4] = *(const float4*)(vrow + i * 4);
        __syncthreads();
        #pragma unroll 8
        for (int k = 0; k < 64; ++k) {
            float a[4];
            #pragma unroll
            for (int i = 0; i < 4; ++i) a[i] = As[tr + i][k];
            float4 bv = *(const float4*)&Bs[k][tc];
            float br[4] = {bv.x, bv.y, bv.z, bv.w};
            #pragma unroll
            for (int i = 0; i < 4; ++i)
                #pragma unroll
                for (int j = 0; j < 4; ++j) acc[i][j] += a[i] * br[j];
        }
        __syncthreads();
    }
    #pragma unroll
    for (int i = 0; i < 4; ++i) {
        float* orow = g_ao + (size_t)(b * T_ + tt * 64 + tr + i) * D_ + h * 64 + tc;
        #pragma unroll
        for (int j = 0; j < 4; ++j) orow[j] = acc[i][j];
    }
}

// ---------------- SO(2) rotate + layernorm(HID) + SiLU, in-place on g_h ----------------
__global__ __launch_bounds__(256) void rot_k(const float* __restrict__ theta,
                                             const float* __restrict__ g,
                                             const float* __restrict__ bb) {
    int row = blockIdx.x;
    float* hrow = g_h + (size_t)row * HID_;
    int tid = threadIdx.x;
    float r0[6], r1[6];
    float s = 0.f, sq = 0.f;
    #pragma unroll
    for (int i = 0; i < 6; ++i) {
        int p = tid + i * 256;                    // HID/2 = 1536 = 256*6
        float2 ab = *(const float2*)(hrow + 2 * p);
        float sn, cs;
        sincosf(theta[p], &sn, &cs);
        r0[i] = cs * ab.x - sn * ab.y;
        r1[i] = sn * ab.x + cs * ab.y;
        s += r0[i] + r1[i];
        sq += r0[i] * r0[i] + r1[i] * r1[i];
    }
    float2 r = block_reduce2(s, sq);
    float mu = r.x * (1.0f / HID_);
    float var = r.y * (1.0f / HID_) - mu * mu;
    float inv = rsqrtf(var + 1e-5f);
    #pragma unroll
    for (int i = 0; i < 6; ++i) {
        int p = tid + i * 256;
        int e0 = 2 * p, e1 = 2 * p + 1;
        float y0 = (r0[i] - mu) * inv * g[e0] + bb[e0];
        float y1 = (r1[i] - mu) * inv * g[e1] + bb[e1];
        y0 = y0 / (1.0f + expf(-y0));
        y1 = y1 / (1.0f + expf(-y1));
        float2 o = make_float2(y0, y1);
        *(float2*)(hrow + 2 * p) = o;
    }
}

// ---------------- host launcher ----------------
extern "C" void kernel_launch(void* const* d_in, const int* in_sizes, int n_in,
                              void* d_out, int out_size) {
    const float* x   = (const float*)d_in[0];
    const float* wq  = (const float*)d_in[1];
    const float* wk  = (const float*)d_in[2];
    const float* wv  = (const float*)d_in[3];
    const float* wo  = (const float*)d_in[4];
    const float* su  = (const float*)d_in[5];
    const float* sv  = (const float*)d_in[6];
    const float* ps  = (const float*)d_in[7];
    const float* n1g = (const float*)d_in[8];
    const float* n1b = (const float*)d_in[9];
    const float* n2g = (const float*)d_in[10];
    const float* n2b = (const float*)d_in[11];
    const float* wup = (const float*)d_in[12];
    const float* wdn = (const float*)d_in[13];
    const float* th  = (const float*)d_in[14];
    const float* mng = (const float*)d_in[15];
    const float* mnb = (const float*)d_in[16];
    float* out = (float*)d_out;

    float *qwq, *qwk, *qwv, *qwo, *qsu, *qsv, *fwq, *fwk, *qup, *qdn, *xn, *Qb, *Kb, *Vb, *ao, *hb;
    cudaGetSymbolAddress((void**)&qwq, g_qwq);
    cudaGetSymbolAddress((void**)&qwk, g_qwk);
    cudaGetSymbolAddress((void**)&qwv, g_qwv);
    cudaGetSymbolAddress((void**)&qwo, g_qwo);
    cudaGetSymbolAddress((void**)&qsu, g_qsu);
    cudaGetSymbolAddress((void**)&qsv, g_qsv);
    cudaGetSymbolAddress((void**)&fwq, g_fwq);
    cudaGetSymbolAddress((void**)&fwk, g_fwk);
    cudaGetSymbolAddress((void**)&qup, g_qup);
    cudaGetSymbolAddress((void**)&qdn, g_qdn);
    cudaGetSymbolAddress((void**)&xn, g_xn);
    cudaGetSymbolAddress((void**)&Qb, g_Q);
    cudaGetSymbolAddress((void**)&Kb, g_K);
    cudaGetSymbolAddress((void**)&Vb, g_V);
    cudaGetSymbolAddress((void**)&ao, g_ao);
    cudaGetSymbolAddress((void**)&hb, g_h);

    const int nDD = D_ * D_;            // 1048576
    const int nSS = S_ * S_;            // 4096
    const int nUP = HID_ * D_;          // 3145728

    // 1) quantize all weights
    reset_k<<<1, 32>>>();
    absmax_k<<<1024, 256>>>(wq, nDD, 0);
    absmax_k<<<1024, 256>>>(wk, nDD, 1);
    absmax_k<<<1024, 256>>>(wv, nDD, 2);
    absmax_k<<<1024, 256>>>(wo, nDD, 3);
    absmax_k<<<16, 256>>>(su, nSS, 4);
    absmax_k<<<16, 256>>>(sv, nSS, 5);
    absmax_k<<<2048, 256>>>(wup, nUP, 6);
    absmax_k<<<2048, 256>>>(wdn, nUP, 7);
    quant_k<<<(nDD + 255) / 256, 256>>>(wq, qwq, nDD, 0);
    quant_k<<<(nDD + 255) / 256, 256>>>(wk, qwk, nDD, 1);
    quant_k<<<(nDD + 255) / 256, 256>>>(wv, qwv, nDD, 2);
    quant_k<<<(nDD + 255) / 256, 256>>>(wo, qwo, nDD, 3);
    quant_k<<<(nSS + 255) / 256, 256>>>(su, qsu, nSS, 4);
    quant_k<<<(nSS + 255) / 256, 256>>>(sv, qsv, nSS, 5);
    quant_k<<<(nUP + 255) / 256, 256>>>(wup, qup, nUP, 6);
    quant_k<<<(nUP + 255) / 256, 256>>>(wdn, qdn, nUP, 7);

    // 2) fold stalk maps into Q/K projection weights
    fuse_stalk_k<<<dim3(D_ / 128, H_), 256>>>(qsu, qwq, fwq);
    fuse_stalk_k<<<dim3(D_ / 128, H_), 256>>>(qsv, qwk, fwk);

    // 3) attention half
    ln_k<<<NTOK, 256>>>(x, n1g, n1b, xn);
    sgemm_nt<<<dim3(D_ / 128, NTOK / 128), 256>>>(xn, fwq, nullptr, Qb, NTOK, D_, D_);
    sgemm_nt<<<dim3(D_ / 128, NTOK / 128), 256>>>(xn, fwk, nullptr, Kb, NTOK, D_, D_);
    sgemm_nt<<<dim3(D_ / 128, NTOK / 128), 256>>>(xn, qwv, nullptr, Vb, NTOK, D_, D_);
    scores_k<<<dim3(T_ / 64, T_ / 64, B_ * H_), 256>>>(ps);
    softmax_k<<<dim3(T_, B_ * H_), 128>>>();
    av_k<<<dim3(T_ / 64, B_ * H_), 256>>>();
    sgemm_nt<<<dim3(D_ / 128, NTOK / 128), 256>>>(ao, qwo, x, out, NTOK, D_, D_);

    // 4) MLP half
    ln_k<<<NTOK, 256>>>(out, n2g, n2b, xn);
    sgemm_nt<<<dim3(HID_ / 128, NTOK / 128), 256>>>(xn, qup, nullptr, hb, NTOK, HID_, D_);
    rot_k<<<NTOK, 256>>>(th, mng, mnb);
    sgemm_nt<<<dim3(D_ / 128, NTOK / 128), 256>>>(hb, qdn, out, out, NTOK, D_, HID_);
}

// round 3
// speedup vs baseline: 2.1353x; 2.1353x over previous
#include <cuda_runtime.h>
#include <cuda_bf16.h>
#include <math.h>
#include <stdint.h>

// ---------------- problem constants ----------------
#define B_ 4
#define T_ 1024
#define D_ 1024
#define H_ 16
#define S_ 64
#define HID_ 3072
#define NTOK (B_*T_)            // 4096

// ---------------- device scratch (static, allowed) ----------------
__device__ float g_qwq[D_*D_];
__device__ float g_qwk[D_*D_];
__device__ float g_qwv[D_*D_];
__device__ float g_qwo[D_*D_];
__device__ float g_qsu[S_*S_];
__device__ float g_qsv[S_*S_];
__device__ float g_fwq[D_*D_];          // blockdiag(su_q) @ wq_q
__device__ float g_fwk[D_*D_];          // blockdiag(sv_q) @ wk_q
__device__ float g_qup[HID_*D_];
__device__ float g_qdn[D_*HID_];
__device__ float g_xn[NTOK*D_];
__device__ float g_Q[NTOK*D_];
__device__ float g_K[NTOK*D_];
__device__ float g_V[NTOK*D_];
__device__ float g_ao[NTOK*D_];
__device__ float g_h[NTOK*HID_];
__device__ float g_sc[(size_t)B_*H_*T_*T_];   // 256 MB score/attn buffer
__device__ unsigned g_maxabs[8];

// bf16 3-term split buffers (A-side: hi|lo|hi, B-side: hi|hi|lo)
__device__ __nv_bfloat16 e_x [(size_t)NTOK*3*D_];
__device__ __nv_bfloat16 e_h [(size_t)NTOK*3*HID_];
__device__ __nv_bfloat16 e_wq[(size_t)D_*3*D_];
__device__ __nv_bfloat16 e_wk[(size_t)D_*3*D_];
__device__ __nv_bfloat16 e_wv[(size_t)D_*3*D_];
__device__ __nv_bfloat16 e_wo[(size_t)D_*3*D_];
__device__ __nv_bfloat16 e_up[(size_t)HID_*3*D_];
__device__ __nv_bfloat16 e_dn[(size_t)D_*3*HID_];

// ---------------- PTX helpers ----------------
__device__ __forceinline__ uint32_t s2u(const void* p) {
    uint32_t a;
    asm("{ .reg .u64 t; cvta.to.shared.u64 t, %1; cvt.u32.u64 %0, t; }" : "=r"(a) : "l"(p));
    return a;
}
__device__ __forceinline__ void ldsm4(uint32_t* r, uint32_t a) {
    asm volatile("ldmatrix.sync.aligned.m8n8.x4.shared.b16 {%0,%1,%2,%3}, [%4];"
        : "=r"(r[0]), "=r"(r[1]), "=r"(r[2]), "=r"(r[3]) : "r"(a));
}
__device__ __forceinline__ void ldsm2(uint32_t* r, uint32_t a) {
    asm volatile("ldmatrix.sync.aligned.m8n8.x2.shared.b16 {%0,%1}, [%2];"
        : "=r"(r[0]), "=r"(r[1]) : "r"(a));
}
__device__ __forceinline__ void mma16816(float* c, const uint32_t* a, const uint32_t* b) {
    asm volatile("mma.sync.aligned.m16n8k16.row.col.f32.bf16.bf16.f32 "
        "{%0,%1,%2,%3}, {%4,%5,%6,%7}, {%8,%9}, {%0,%1,%2,%3};"
        : "+f"(c[0]), "+f"(c[1]), "+f"(c[2]), "+f"(c[3])
        : "r"(a[0]), "r"(a[1]), "r"(a[2]), "r"(a[3]), "r"(b[0]), "r"(b[1]));
}
__device__ __forceinline__ void cpasync16(uint32_t dst, const void* src) {
    asm volatile("cp.async.cg.shared.global [%0], [%1], 16;" :: "r"(dst), "l"(src));
}

// ---------------- bf16 HMMA GEMM: C[M,N] = A_ext[M,K3] @ B_ext[N,K3]^T (+Res) ----------------
// CTA tile 128x128, 8 warps (2x4), warp tile 64x32, K-chunk 64, double-buffered cp.async.
#define MMX_SMEM 65536

__global__ __launch_bounds__(256) void mm_hmma(const __nv_bfloat16* __restrict__ Ag,
                                               const __nv_bfloat16* __restrict__ Bg,
                                               const float* __restrict__ Res,
                                               float* __restrict__ C,
                                               int M, int N, int K3) {
    extern __shared__ char sm_[];
    uint32_t sbase = s2u(sm_);
    int tid = threadIdx.x, lane = tid & 31, wid = tid >> 5;
    int wm = wid >> 2, wn = wid & 3;
    int m0 = blockIdx.y * 128, n0 = blockIdx.x * 128;
    const __nv_bfloat16* Ap = Ag + (size_t)m0 * K3;
    const __nv_bfloat16* Bp = Bg + (size_t)n0 * K3;
    int NC = K3 >> 6;

    float c[4][4][4];
    #pragma unroll
    for (int i = 0; i < 4; ++i)
        #pragma unroll
        for (int j = 0; j < 4; ++j)
            #pragma unroll
            for (int e = 0; e < 4; ++e) c[i][j][e] = 0.f;

    // per-thread copy coords (16B grains): row 0..127, chunk 0..7
    int crow = tid >> 3, cch = tid & 7;

    // issue one chunk's cp.async (A tile 128x64 bf16 + B tile 128x64 bf16)
    #define COPY_CHUNK(cidx, buf) do {                                             \
        uint32_t Ab_ = sbase + (buf) * 32768;                                      \
        uint32_t Bb_ = Ab_ + 16384;                                                \
        int kc_ = (cidx) << 6;                                                     \
        _Pragma("unroll")                                                          \
        for (int i_ = 0; i_ < 4; ++i_) {                                           \
            int row_ = crow + i_ * 32;                                             \
            uint32_t dst_ = Ab_ + row_ * 128 + (((cch) ^ (row_ & 7)) << 4);        \
            cpasync16(dst_, Ap + (size_t)row_ * K3 + kc_ + cch * 8);               \
        }                                                                          \
        _Pragma("unroll")                                                          \
        for (int i_ = 0; i_ < 4; ++i_) {                                           \
            int row_ = crow + i_ * 32;                                             \
            uint32_t dst_ = Bb_ + row_ * 128 + (((cch) ^ (row_ & 7)) << 4);        \
            cpasync16(dst_, Bp + (size_t)row_ * K3 + kc_ + cch * 8);               \
        }                                                                          \
        asm volatile("cp.async.commit_group;" ::: "memory");                       \
    } while (0)

    COPY_CHUNK(0, 0);

    for (int c0 = 0; c0 < NC; ++c0) {
        int buf = c0 & 1;
        if (c0 + 1 < NC) {
            COPY_CHUNK(c0 + 1, buf ^ 1);
            asm volatile("cp.async.wait_group 1;" ::: "memory");
        } else {
            asm volatile("cp.async.wait_group 0;" ::: "memory");
        }
        __syncthreads();
        uint32_t Ab = sbase + buf * 32768;
        uint32_t Bb = Ab + 16384;
        #pragma unroll
        for (int ks = 0; ks < 4; ++ks) {
            uint32_t a[4][4], b[4][2];
            #pragma unroll
            for (int i = 0; i < 4; ++i) {
                int row = wm * 64 + i * 16 + (lane & 15);
                int ch = ks * 2 + (lane >> 4);
                ldsm4(a[i], Ab + row * 128 + ((ch ^ (row & 7)) << 4));
            }
            #pragma unroll
            for (int j = 0; j < 4; ++j) {
                int row = wn * 32 + j * 8 + (lane & 7);
                int ch = ks * 2 + ((lane >> 3) & 1);
                ldsm2(b[j], Bb + row * 128 + ((ch ^ (row & 7)) << 4));
            }
            #pragma unroll
            for (int i = 0; i < 4; ++i)
                #pragma unroll
                for (int j = 0; j < 4; ++j)
                    mma16816(c[i][j], a[i], b[j]);
        }
        __syncthreads();
    }
    #undef COPY_CHUNK

    // epilogue: c0,c1 -> (row, col..col+1); c2,c3 -> (row+8, col..col+1)
    int g = lane >> 2, tg = lane & 3;
    #pragma unroll
    for (int i = 0; i < 4; ++i) {
        int r0 = m0 + wm * 64 + i * 16 + g;
        #pragma unroll
        for (int j = 0; j < 4; ++j) {
            int cc = n0 + wn * 32 + j * 8 + tg * 2;
            float* p0 = C + (size_t)r0 * N + cc;
            float* p1 = C + (size_t)(r0 + 8) * N + cc;
            if (Res) {
                const float* q0 = Res + (size_t)r0 * N + cc;
                const float* q1 = Res + (size_t)(r0 + 8) * N + cc;
                float2 v0 = *(const float2*)q0;
                float2 v1 = *(const float2*)q1;
                float2 o0 = make_float2(c[i][j][0] + v0.x, c[i][j][1] + v0.y);
                float2 o1 = make_float2(c[i][j][2] + v1.x, c[i][j][3] + v1.y);
                *(float2*)p0 = o0;
                *(float2*)p1 = o1;
            } else {
                *(float2*)p0 = make_float2(c[i][j][0], c[i][j][1]);
                *(float2*)p1 = make_float2(c[i][j][2], c[i][j][3]);
            }
        }
    }
}

// ---------------- fp32 -> bf16 3-term split ----------------
// mode 0 (A-side): [hi | lo | hi]     mode 1 (B-side): [hi | hi | lo]
__global__ __launch_bounds__(256) void split_k(const float* __restrict__ in,
                                               __nv_bfloat16* __restrict__ out,
                                               int K, int mode, int total) {
    int idx = blockIdx.x * blockDim.x + threadIdx.x;
    if (idx >= total) return;
    int m = idx / K, k = idx - m * K;
    float x = in[idx];
    __nv_bfloat16 h = __float2bfloat16(x);
    __nv_bfloat16 l = __float2bfloat16(x - __bfloat162float(h));
    size_t bse = (size_t)m * (3 * K) + k;
    if (mode == 0) {
        out[bse] = h; out[bse + K] = l; out[bse + 2 * K] = h;
    } else {
        out[bse] = h; out[bse + K] = h; out[bse + 2 * K] = l;
    }
}

// ---------------- small helpers ----------------
__device__ __forceinline__ float2 block_reduce2(float a, float b) {
    #pragma unroll
    for (int o = 16; o; o >>= 1) {
        a += __shfl_xor_sync(0xffffffffu, a, o);
        b += __shfl_xor_sync(0xffffffffu, b, o);
    }
    __shared__ float sa[8], sb[8];
    int w = threadIdx.x >> 5, l = threadIdx.x & 31;
    int nw = (blockDim.x + 31) >> 5;
    if (l == 0) { sa[w] = a; sb[w] = b; }
    __syncthreads();
    if (w == 0) {
        a = (l < nw) ? sa[l] : 0.f;
        b = (l < nw) ? sb[l] : 0.f;
        #pragma unroll
        for (int o = 4; o; o >>= 1) {
            a += __shfl_xor_sync(0xffffffffu, a, o);
            b += __shfl_xor_sync(0xffffffffu, b, o);
        }
        if (l == 0) { sa[0] = a; sb[0] = b; }
    }
    __syncthreads();
    return make_float2(sa[0], sb[0]);
}

// ---------------- quantization ----------------
__global__ void reset_k() {
    if (threadIdx.x < 8) g_maxabs[threadIdx.x] = 0u;
}

__global__ __launch_bounds__(256) void absmax_k(const float* __restrict__ w, int n, int slot) {
    float m = 0.f;
    for (int i = blockIdx.x * blockDim.x + threadIdx.x; i < n; i += gridDim.x * blockDim.x)
        m = fmaxf(m, fabsf(w[i]));
    #pragma unroll
    for (int o = 16; o; o >>= 1) m = fmaxf(m, __shfl_xor_sync(0xffffffffu, m, o));
    __shared__ float sm[8];
    if ((threadIdx.x & 31) == 0) sm[threadIdx.x >> 5] = m;
    __syncthreads();
    if (threadIdx.x < 8) {
        m = sm[threadIdx.x];
        #pragma unroll
        for (int o = 4; o; o >>= 1) m = fmaxf(m, __shfl_xor_sync(0xffu, m, o));
        if (threadIdx.x == 0) atomicMax(&g_maxabs[slot], __float_as_uint(m));
    }
}

__global__ __launch_bounds__(256) void quant_k(const float* __restrict__ w, float* __restrict__ out,
                                               int n, int slot) {
    float scale = __uint_as_float(g_maxabs[slot]) / 31.0f + 1e-8f;
    int i = blockIdx.x * blockDim.x + threadIdx.x;
    if (i < n) {
        float q = rintf(w[i] / scale);
        q = fminf(fmaxf(q, -31.f), 31.f);
        out[i] = q * scale;
    }
}

// fw[h*64+s][k] = sum_j su[s][j] * w[h*64+j][k]
__global__ __launch_bounds__(256) void fuse_stalk_k(const float* __restrict__ su,
                                                    const float* __restrict__ w,
                                                    float* __restrict__ fw) {
    __shared__ float Ws[64][128];
    __shared__ float Ss[64][64];
    int h = blockIdx.y;
    int k0 = blockIdx.x * 128;
    int tid = threadIdx.x;
    #pragma unroll
    for (int it = 0; it < 8; ++it) {
        int chunk = tid + it * 256;
        int r = chunk >> 5, c4 = (chunk & 31) * 4;
        float4 v = *(const float4*)(w + (size_t)(h * 64 + r) * D_ + k0 + c4);
        *(float4*)&Ws[r][c4] = v;
    }
    #pragma unroll
    for (int it = 0; it < 4; ++it) {
        int chunk = tid + it * 256;
        int r = chunk >> 4, c4 = (chunk & 15) * 4;
        float4 v = *(const float4*)(su + (size_t)r * 64 + c4);
        *(float4*)&Ss[r][c4] = v;
    }
    __syncthreads();
    #pragma unroll 4
    for (int it = 0; it < 32; ++it) {
        int oidx = tid + it * 256;
        int s = oidx >> 7, kk = oidx & 127;
        float acc = 0.f;
        #pragma unroll
        for (int j = 0; j < 64; ++j) acc += Ss[s][j] * Ws[j][kk];
        fw[(size_t)(h * 64 + s) * D_ + k0 + kk] = acc;
    }
}

// ---------------- layernorm over D=1024 ----------------
__global__ __launch_bounds__(256) void ln_k(const float* __restrict__ x, const float* __restrict__ g,
                                            const float* __restrict__ bb, float* __restrict__ out) {
    int row = blockIdx.x;
    const float* xr = x + (size_t)row * D_;
    int c = threadIdx.x * 4;
    float4 v = *(const float4*)(xr + c);
    float s = v.x + v.y + v.z + v.w;
    float sq = v.x * v.x + v.y * v.y + v.z * v.z + v.w * v.w;
    float2 r = block_reduce2(s, sq);
    float mu = r.x * (1.0f / D_);
    float var = r.y * (1.0f / D_) - mu * mu;
    float inv = rsqrtf(var + 1e-5f);
    float4 gg = *(const float4*)(g + c);
    float4 bv = *(const float4*)(bb + c);
    float4 o;
    o.x = (v.x - mu) * inv * gg.x + bv.x;
    o.y = (v.y - mu) * inv * gg.y + bv.y;
    o.z = (v.z - mu) * inv * gg.z + bv.z;
    o.w = (v.w - mu) * inv * gg.w + bv.w;
    *(float4*)(out + (size_t)row * D_ + c) = o;
}

// ---------------- scores ----------------
__global__ __launch_bounds__(256) void scores_k(const float* __restrict__ p_scale) {
    int ut = blockIdx.x, tt = blockIdx.y, bh = blockIdx.z;
    if (ut > tt) return;
    int b = bh >> 4, h = bh & 15;
    __shared__ float Qs[64][67];
    __shared__ float Ks[64][67];
    int tid = threadIdx.x;
    int lr = tid >> 2, lc = (tid & 3) * 16;
    {
        const float* qb = g_Q + (size_t)(b * T_ + tt * 64 + lr) * D_ + h * 64 + lc;
        const float* kb = g_K + (size_t)(b * T_ + ut * 64 + lr) * D_ + h * 64 + lc;
        #pragma unroll
        for (int i = 0; i < 4; ++i) {
            float4 qv = *(const float4*)(qb + i * 4);
            float4 kv = *(const float4*)(kb + i * 4);
            Qs[lr][lc + i * 4 + 0] = qv.x; Qs[lr][lc + i * 4 + 1] = qv.y;
            Qs[lr][lc + i * 4 + 2] = qv.z; Qs[lr][lc + i * 4 + 3] = qv.w;
            Ks[lr][lc + i * 4 + 0] = kv.x; Ks[lr][lc + i * 4 + 1] = kv.y;
            Ks[lr][lc + i * 4 + 2] = kv.z; Ks[lr][lc + i * 4 + 3] = kv.w;
        }
    }
    __syncthreads();
    int tr = (tid >> 4) * 4, tc = (tid & 15) * 4;
    float acc[4][4] = {};
    #pragma unroll 16
    for (int k = 0; k < 64; ++k) {
        float qr[4], kr[4];
        #pragma unroll
        for (int i = 0; i < 4; ++i) qr[i] = Qs[tr + i][k];
        #pragma unroll
        for (int j = 0; j < 4; ++j) kr[j] = Ks[tc + j][k];
        #pragma unroll
        for (int i = 0; i < 4; ++i)
            #pragma unroll
            for (int j = 0; j < 4; ++j) acc[i][j] += qr[i] * kr[j];
    }
    float ps = p_scale[0];
    #pragma unroll
    for (int i = 0; i < 4; ++i) {
        int t = tt * 64 + tr + i;
        float* row = g_sc + ((size_t)bh * T_ + t) * T_;
        #pragma unroll
        for (int j = 0; j < 4; ++j) {
            int u = ut * 64 + tc + j;
            int d = t - u; d = d < 0 ? -d : d;
            float bias;
            if (d == 0) bias = 1.0f;
            else {
                int vp = __ffs(d) - 1;
                vp = vp > 16 ? 16 : vp;
                bias = (float)vp * (1.0f / 16.0f);
            }
            row[u] = acc[i][j] * 0.125f + ps * bias;
        }
    }
}

// ---------------- causal softmax ----------------
__global__ __launch_bounds__(128) void softmax_k() {
    int t = blockIdx.x, bh = blockIdx.y;
    float* row = g_sc + ((size_t)bh * T_ + t) * T_;
    int tid = threadIdx.x;
    float v[8];
    float mx = -INFINITY;
    #pragma unroll
    for (int i = 0; i < 8; ++i) {
        int u = tid + i * 128;
        v[i] = (u <= t) ? row[u] : -INFINITY;
        mx = fmaxf(mx, v[i]);
    }
    __shared__ float red[4];
    #pragma unroll
    for (int o = 16; o; o >>= 1) mx = fmaxf(mx, __shfl_xor_sync(0xffffffffu, mx, o));
    if ((tid & 31) == 0) red[tid >> 5] = mx;
    __syncthreads();
    mx = fmaxf(fmaxf(red[0], red[1]), fmaxf(red[2], red[3]));
    float sum = 0.f;
    #pragma unroll
    for (int i = 0; i < 8; ++i) {
        float e = expf(v[i] - mx);
        v[i] = e;
        sum += e;
    }
    __shared__ float red2[4];
    #pragma unroll
    for (int o = 16; o; o >>= 1) sum += __shfl_xor_sync(0xffffffffu, sum, o);
    if ((tid & 31) == 0) red2[tid >> 5] = sum;
    __syncthreads();
    sum = red2[0] + red2[1] + red2[2] + red2[3];
    float inv = 1.0f / sum;
    int fillEnd = ((t >> 6) + 1) << 6;
    #pragma unroll
    for (int i = 0; i < 8; ++i) {
        int u = tid + i * 128;
        if (u <= t) row[u] = v[i] * inv;
        else if (u < fillEnd) row[u] = 0.f;
    }
}

// ---------------- out = attn @ V ----------------
__global__ __launch_bounds__(256) void av_k() {
    int tt = blockIdx.x, bh = blockIdx.y;
    int b = bh >> 4, h = bh & 15;
    __shared__ float As[64][68];
    __shared__ float Bs[64][68];
    int tid = threadIdx.x;
    int lr = tid >> 2, lc = (tid & 3) * 16;
    int tr = (tid >> 4) * 4, tc = (tid & 15) * 4;
    float acc[4][4] = {};
    const float* arow = g_sc + ((size_t)bh * T_ + tt * 64 + lr) * T_ + lc;
    for (int u0 = 0; u0 <= tt * 64; u0 += 64) {
        #pragma unroll
        for (int i = 0; i < 4; ++i)
            *(float4*)&As[lr][lc + i * 4] = *(const float4*)(arow + u0 + i * 4);
        const float* vrow = g_V + (size_t)(b * T_ + u0 + lr) * D_ + h * 64 + lc;
        #pragma unroll
        for (int i = 0; i < 4; ++i)
            *(float4*)&Bs[lr][lc + i * 4] = *(const float4*)(vrow + i * 4);
        __syncthreads();
        #pragma unroll 8
        for (int k = 0; k < 64; ++k) {
            float a[4];
            #pragma unroll
            for (int i = 0; i < 4; ++i) a[i] = As[tr + i][k];
            float4 bv = *(const float4*)&Bs[k][tc];
            float br[4] = {bv.x, bv.y, bv.z, bv.w};
            #pragma unroll
            for (int i = 0; i < 4; ++i)
                #pragma unroll
                for (int j = 0; j < 4; ++j) acc[i][j] += a[i] * br[j];
        }
        __syncthreads();
    }
    #pragma unroll
    for (int i = 0; i < 4; ++i) {
        float* orow = g_ao + (size_t)(b * T_ + tt * 64 + tr + i) * D_ + h * 64 + tc;
        #pragma unroll
        for (int j = 0; j < 4; ++j) orow[j] = acc[i][j];
    }
}

// ---------------- SO(2) rotate + layernorm(HID) + SiLU ----------------
__global__ __launch_bounds__(256) void rot_k(const float* __restrict__ theta,
                                             const float* __restrict__ g,
                                             const float* __restrict__ bb) {
    int row = blockIdx.x;
    float* hrow = g_h + (size_t)row * HID_;
    int tid = threadIdx.x;
    float r0[6], r1[6];
    float s = 0.f, sq = 0.f;
    #pragma unroll
    for (int i = 0; i < 6; ++i) {
        int p = tid + i * 256;
        float2 ab = *(const float2*)(hrow + 2 * p);
        float sn, cs;
        sincosf(theta[p], &sn, &cs);
        r0[i] = cs * ab.x - sn * ab.y;
        r1[i] = sn * ab.x + cs * ab.y;
        s += r0[i] + r1[i];
        sq += r0[i] * r0[i] + r1[i] * r1[i];
    }
    float2 r = block_reduce2(s, sq);
    float mu = r.x * (1.0f / HID_);
    float var = r.y * (1.0f / HID_) - mu * mu;
    float inv = rsqrtf(var + 1e-5f);
    #pragma unroll
    for (int i = 0; i < 6; ++i) {
        int p = tid + i * 256;
        int e0 = 2 * p, e1 = 2 * p + 1;
        float y0 = (r0[i] - mu) * inv * g[e0] + bb[e0];
        float y1 = (r1[i] - mu) * inv * g[e1] + bb[e1];
        y0 = y0 / (1.0f + expf(-y0));
        y1 = y1 / (1.0f + expf(-y1));
        float2 o = make_float2(y0, y1);
        *(float2*)(hrow + 2 * p) = o;
    }
}

// ---------------- host launcher ----------------
extern "C" void kernel_launch(void* const* d_in, const int* in_sizes, int n_in,
                              void* d_out, int out_size) {
    const float* x   = (const float*)d_in[0];
    const float* wq  = (const float*)d_in[1];
    const float* wk  = (const float*)d_in[2];
    const float* wv  = (const float*)d_in[3];
    const float* wo  = (const float*)d_in[4];
    const float* su  = (const float*)d_in[5];
    const float* sv  = (const float*)d_in[6];
    const float* ps  = (const float*)d_in[7];
    const float* n1g = (const float*)d_in[8];
    const float* n1b = (const float*)d_in[9];
    const float* n2g = (const float*)d_in[10];
    const float* n2b = (const float*)d_in[11];
    const float* wup = (const float*)d_in[12];
    const float* wdn = (const float*)d_in[13];
    const float* th  = (const float*)d_in[14];
    const float* mng = (const float*)d_in[15];
    const float* mnb = (const float*)d_in[16];
    float* out = (float*)d_out;

    float *qwq, *qwk, *qwv, *qwo, *qsu, *qsv, *fwq, *fwk, *qup, *qdn, *xn, *Qb, *Kb, *Vb, *ao, *hb;
    __nv_bfloat16 *ex, *eh, *ewq, *ewk, *ewv, *ewo, *eup, *edn;
    cudaGetSymbolAddress((void**)&qwq, g_qwq);
    cudaGetSymbolAddress((void**)&qwk, g_qwk);
    cudaGetSymbolAddress((void**)&qwv, g_qwv);
    cudaGetSymbolAddress((void**)&qwo, g_qwo);
    cudaGetSymbolAddress((void**)&qsu, g_qsu);
    cudaGetSymbolAddress((void**)&qsv, g_qsv);
    cudaGetSymbolAddress((void**)&fwq, g_fwq);
    cudaGetSymbolAddress((void**)&fwk, g_fwk);
    cudaGetSymbolAddress((void**)&qup, g_qup);
    cudaGetSymbolAddress((void**)&qdn, g_qdn);
    cudaGetSymbolAddress((void**)&xn, g_xn);
    cudaGetSymbolAddress((void**)&Qb, g_Q);
    cudaGetSymbolAddress((void**)&Kb, g_K);
    cudaGetSymbolAddress((void**)&Vb, g_V);
    cudaGetSymbolAddress((void**)&ao, g_ao);
    cudaGetSymbolAddress((void**)&hb, g_h);
    cudaGetSymbolAddress((void**)&ex, e_x);
    cudaGetSymbolAddress((void**)&eh, e_h);
    cudaGetSymbolAddress((void**)&ewq, e_wq);
    cudaGetSymbolAddress((void**)&ewk, e_wk);
    cudaGetSymbolAddress((void**)&ewv, e_wv);
    cudaGetSymbolAddress((void**)&ewo, e_wo);
    cudaGetSymbolAddress((void**)&eup, e_up);
    cudaGetSymbolAddress((void**)&edn, e_dn);

    static bool attr_set = false;
    if (!attr_set) {
        cudaFuncSetAttribute(mm_hmma, cudaFuncAttributeMaxDynamicSharedMemorySize, MMX_SMEM);
        attr_set = true;
    }

    const int nDD = D_ * D_;
    const int nSS = S_ * S_;
    const int nUP = HID_ * D_;

    // 1) quantize all weights (fp32)
    reset_k<<<1, 32>>>();
    absmax_k<<<1024, 256>>>(wq, nDD, 0);
    absmax_k<<<1024, 256>>>(wk, nDD, 1);
    absmax_k<<<1024, 256>>>(wv, nDD, 2);
    absmax_k<<<1024, 256>>>(wo, nDD, 3);
    absmax_k<<<16, 256>>>(su, nSS, 4);
    absmax_k<<<16, 256>>>(sv, nSS, 5);
    absmax_k<<<2048, 256>>>(wup, nUP, 6);
    absmax_k<<<2048, 256>>>(wdn, nUP, 7);
    quant_k<<<(nDD + 255) / 256, 256>>>(wq, qwq, nDD, 0);
    quant_k<<<(nDD + 255) / 256, 256>>>(wk, qwk, nDD, 1);
    quant_k<<<(nDD + 255) / 256, 256>>>(wv, qwv, nDD, 2);
    quant_k<<<(nDD + 255) / 256, 256>>>(wo, qwo, nDD, 3);
    quant_k<<<(nSS + 255) / 256, 256>>>(su, qsu, nSS, 4);
    quant_k<<<(nSS + 255) / 256, 256>>>(sv, qsv, nSS, 5);
    quant_k<<<(nUP + 255) / 256, 256>>>(wup, qup, nUP, 6);
    quant_k<<<(nUP + 255) / 256, 256>>>(wdn, qdn, nUP, 7);

    // 2) fold stalk maps into Q/K projection weights
    fuse_stalk_k<<<dim3(D_ / 128, H_), 256>>>(qsu, qwq, fwq);
    fuse_stalk_k<<<dim3(D_ / 128, H_), 256>>>(qsv, qwk, fwk);

    // 3) bf16 3-term splits of weights (B-side layout)
    split_k<<<(nDD + 255) / 256, 256>>>(fwq, ewq, D_, 1, nDD);
    split_k<<<(nDD + 255) / 256, 256>>>(fwk, ewk, D_, 1, nDD);
    split_k<<<(nDD + 255) / 256, 256>>>(qwv, ewv, D_, 1, nDD);
    split_k<<<(nDD + 255) / 256, 256>>>(qwo, ewo, D_, 1, nDD);
    split_k<<<(nUP + 255) / 256, 256>>>(qup, eup, D_, 1, nUP);
    split_k<<<(nUP + 255) / 256, 256>>>(qdn, edn, HID_, 1, nUP);

    // 4) attention half
    ln_k<<<NTOK, 256>>>(x, n1g, n1b, xn);
    split_k<<<(NTOK * D_ + 255) / 256, 256>>>(xn, ex, D_, 0, NTOK * D_);
    mm_hmma<<<dim3(D_ / 128, NTOK / 128), 256, MMX_SMEM>>>(ex, ewq, nullptr, Qb, NTOK, D_, 3 * D_);
    mm_hmma<<<dim3(D_ / 128, NTOK / 128), 256, MMX_SMEM>>>(ex, ewk, nullptr, Kb, NTOK, D_, 3 * D_);
    mm_hmma<<<dim3(D_ / 128, NTOK / 128), 256, MMX_SMEM>>>(ex, ewv, nullptr, Vb, NTOK, D_, 3 * D_);
    scores_k<<<dim3(T_ / 64, T_ / 64, B_ * H_), 256>>>(ps);
    softmax_k<<<dim3(T_, B_ * H_), 128>>>();
    av_k<<<dim3(T_ / 64, B_ * H_), 256>>>();
    split_k<<<(NTOK * D_ + 255) / 256, 256>>>(ao, ex, D_, 0, NTOK * D_);
    mm_hmma<<<dim3(D_ / 128, NTOK / 128), 256, MMX_SMEM>>>(ex, ewo, x, out, NTOK, D_, 3 * D_);

    // 5) MLP half
    ln_k<<<NTOK, 256>>>(out, n2g, n2b, xn);
    split_k<<<(NTOK * D_ + 255) / 256, 256>>>(xn, ex, D_, 0, NTOK * D_);
    mm_hmma<<<dim3(HID_ / 128, NTOK / 128), 256, MMX_SMEM>>>(ex, eup, nullptr, hb, NTOK, HID_, 3 * D_);
    rot_k<<<NTOK, 256>>>(th, mng, mnb);
    split_k<<<(NTOK * HID_ + 255) / 256, 256>>>(hb, eh, HID_, 0, NTOK * HID_);
    mm_hmma<<<dim3(D_ / 128, NTOK / 128), 256, MMX_SMEM>>>(eh, edn, out, out, NTOK, D_, 3 * HID_);
}

// round 4
// speedup vs baseline: 3.0226x; 1.4155x over previous
#include <cuda_runtime.h>
#include <cuda_bf16.h>
#include <math.h>
#include <stdint.h>

// ---------------- problem constants ----------------
#define B_ 4
#define T_ 1024
#define D_ 1024
#define H_ 16
#define S_ 64
#define HID_ 3072
#define NTOK (B_*T_)            // 4096

// ---------------- device scratch ----------------
__device__ float g_qwq[D_*D_];
__device__ float g_qwk[D_*D_];
__device__ float g_qsu[S_*S_];
__device__ float g_qsv[S_*S_];
__device__ float g_fwq[D_*D_];
__device__ float g_fwk[D_*D_];
__device__ float g_h[(size_t)NTOK*HID_];            // QKV output, then MLP hidden (fp32)
__device__ unsigned g_maxabs[8];

// bf16 3-term split buffers
__device__ __nv_bfloat16 e_x  [(size_t)NTOK*3*D_];        // activations A-side
__device__ __nv_bfloat16 e_h  [(size_t)NTOK*3*HID_];      // mlp hidden A-side
__device__ __nv_bfloat16 e_qkv[(size_t)(3*D_)*3*D_];      // fused QKV weights B-side
__device__ __nv_bfloat16 e_wo [(size_t)D_*3*D_];
__device__ __nv_bfloat16 e_up [(size_t)HID_*3*D_];
__device__ __nv_bfloat16 e_dn [(size_t)D_*3*HID_];

// ---------------- PTX helpers ----------------
__device__ __forceinline__ uint32_t s2u(const void* p) {
    uint32_t a;
    asm("{ .reg .u64 t; cvta.to.shared.u64 t, %1; cvt.u32.u64 %0, t; }" : "=r"(a) : "l"(p));
    return a;
}
__device__ __forceinline__ void ldsm4(uint32_t* r, uint32_t a) {
    asm volatile("ldmatrix.sync.aligned.m8n8.x4.shared.b16 {%0,%1,%2,%3}, [%4];"
        : "=r"(r[0]), "=r"(r[1]), "=r"(r[2]), "=r"(r[3]) : "r"(a));
}
__device__ __forceinline__ void ldsm4t(uint32_t* r, uint32_t a) {
    asm volatile("ldmatrix.sync.aligned.m8n8.x4.trans.shared.b16 {%0,%1,%2,%3}, [%4];"
        : "=r"(r[0]), "=r"(r[1]), "=r"(r[2]), "=r"(r[3]) : "r"(a));
}
__device__ __forceinline__ void ldsm2(uint32_t* r, uint32_t a) {
    asm volatile("ldmatrix.sync.aligned.m8n8.x2.shared.b16 {%0,%1}, [%2];"
        : "=r"(r[0]), "=r"(r[1]) : "r"(a));
}
__device__ __forceinline__ void mma16816(float* c, const uint32_t* a, const uint32_t* b) {
    asm volatile("mma.sync.aligned.m16n8k16.row.col.f32.bf16.bf16.f32 "
        "{%0,%1,%2,%3}, {%4,%5,%6,%7}, {%8,%9}, {%0,%1,%2,%3};"
        : "+f"(c[0]), "+f"(c[1]), "+f"(c[2]), "+f"(c[3])
        : "r"(a[0]), "r"(a[1]), "r"(a[2]), "r"(a[3]), "r"(b[0]), "r"(b[1]));
}
__device__ __forceinline__ void cpasync16(uint32_t dst, const void* src) {
    asm volatile("cp.async.cg.shared.global [%0], [%1], 16;" :: "r"(dst), "l"(src));
}
__device__ __forceinline__ uint32_t packbf(float lo, float hi) {
    uint32_t r;
    asm("cvt.rn.bf16x2.f32 %0, %1, %2;" : "=r"(r) : "f"(hi), "f"(lo));
    return r;
}

// ---------------- bf16 HMMA GEMM (unchanged core from R3) ----------------
#define MMX_SMEM 65536
__global__ __launch_bounds__(256) void mm_hmma(const __nv_bfloat16* __restrict__ Ag,
                                               const __nv_bfloat16* __restrict__ Bg,
                                               const float* __restrict__ Res,
                                               float* __restrict__ C,
                                               int M, int N, int K3) {
    extern __shared__ char sm_[];
    uint32_t sbase = s2u(sm_);
    int tid = threadIdx.x, lane = tid & 31, wid = tid >> 5;
    int wm = wid >> 2, wn = wid & 3;
    int m0 = blockIdx.y * 128, n0 = blockIdx.x * 128;
    const __nv_bfloat16* Ap = Ag + (size_t)m0 * K3;
    const __nv_bfloat16* Bp = Bg + (size_t)n0 * K3;
    int NC = K3 >> 6;

    float c[4][4][4];
    #pragma unroll
    for (int i = 0; i < 4; ++i)
        #pragma unroll
        for (int j = 0; j < 4; ++j)
            #pragma unroll
            for (int e = 0; e < 4; ++e) c[i][j][e] = 0.f;

    int crow = tid >> 3, cch = tid & 7;

    #define COPY_CHUNK(cidx, buf) do {                                             \
        uint32_t Ab_ = sbase + (buf) * 32768;                                      \
        uint32_t Bb_ = Ab_ + 16384;                                                \
        int kc_ = (cidx) << 6;                                                     \
        _Pragma("unroll")                                                          \
        for (int i_ = 0; i_ < 4; ++i_) {                                           \
            int row_ = crow + i_ * 32;                                             \
            uint32_t dst_ = Ab_ + row_ * 128 + (((cch) ^ (row_ & 7)) << 4);        \
            cpasync16(dst_, Ap + (size_t)row_ * K3 + kc_ + cch * 8);               \
        }                                                                          \
        _Pragma("unroll")                                                          \
        for (int i_ = 0; i_ < 4; ++i_) {                                           \
            int row_ = crow + i_ * 32;                                             \
            uint32_t dst_ = Bb_ + row_ * 128 + (((cch) ^ (row_ & 7)) << 4);        \
            cpasync16(dst_, Bp + (size_t)row_ * K3 + kc_ + cch * 8);               \
        }                                                                          \
        asm volatile("cp.async.commit_group;" ::: "memory");                       \
    } while (0)

    COPY_CHUNK(0, 0);
    for (int c0 = 0; c0 < NC; ++c0) {
        int buf = c0 & 1;
        if (c0 + 1 < NC) {
            COPY_CHUNK(c0 + 1, buf ^ 1);
            asm volatile("cp.async.wait_group 1;" ::: "memory");
        } else {
            asm volatile("cp.async.wait_group 0;" ::: "memory");
        }
        __syncthreads();
        uint32_t Ab = sbase + buf * 32768;
        uint32_t Bb = Ab + 16384;
        #pragma unroll
        for (int ks = 0; ks < 4; ++ks) {
            uint32_t a[4][4], b[4][2];
            #pragma unroll
            for (int i = 0; i < 4; ++i) {
                int row = wm * 64 + i * 16 + (lane & 15);
                int ch = ks * 2 + (lane >> 4);
                ldsm4(a[i], Ab + row * 128 + ((ch ^ (row & 7)) << 4));
            }
            #pragma unroll
            for (int j = 0; j < 4; ++j) {
                int row = wn * 32 + j * 8 + (lane & 7);
                int ch = ks * 2 + ((lane >> 3) & 1);
                ldsm2(b[j], Bb + row * 128 + ((ch ^ (row & 7)) << 4));
            }
            #pragma unroll
            for (int i = 0; i < 4; ++i)
                #pragma unroll
                for (int j = 0; j < 4; ++j)
                    mma16816(c[i][j], a[i], b[j]);
        }
        __syncthreads();
    }
    #undef COPY_CHUNK

    int g = lane >> 2, tg = lane & 3;
    #pragma unroll
    for (int i = 0; i < 4; ++i) {
        int r0 = m0 + wm * 64 + i * 16 + g;
        #pragma unroll
        for (int j = 0; j < 4; ++j) {
            int cc = n0 + wn * 32 + j * 8 + tg * 2;
            float* p0 = C + (size_t)r0 * N + cc;
            float* p1 = C + (size_t)(r0 + 8) * N + cc;
            if (Res) {
                float2 v0 = *(const float2*)(Res + (size_t)r0 * N + cc);
                float2 v1 = *(const float2*)(Res + (size_t)(r0 + 8) * N + cc);
                *(float2*)p0 = make_float2(c[i][j][0] + v0.x, c[i][j][1] + v0.y);
                *(float2*)p1 = make_float2(c[i][j][2] + v1.x, c[i][j][3] + v1.y);
            } else {
                *(float2*)p0 = make_float2(c[i][j][0], c[i][j][1]);
                *(float2*)p1 = make_float2(c[i][j][2], c[i][j][3]);
            }
        }
    }
}

// ---------------- fused flash attention ----------------
// grid (8 qtiles, 64 bh), 256 threads; smem: Qs[128][200] Ks[64][200] Vh/Vl[64][72] bf16
#define FL_SMEM 95232
__global__ __launch_bounds__(256, 2) void flash_k(const float* __restrict__ qkv,
                                                  const float* __restrict__ p_scale,
                                                  __nv_bfloat16* __restrict__ exo) {
    extern __shared__ char sm_[];
    uint32_t sb = s2u(sm_);
    const uint32_t sQ = sb, sK = sb + 51200, sVh = sb + 76800, sVl = sb + 86016;
    __nv_bfloat16* Qs = (__nv_bfloat16*)sm_;
    __nv_bfloat16* Ks = (__nv_bfloat16*)(sm_ + 51200);
    __nv_bfloat16* Vh = (__nv_bfloat16*)(sm_ + 76800);
    __nv_bfloat16* Vl = (__nv_bfloat16*)(sm_ + 86016);

    int tid = threadIdx.x, lane = tid & 31, wid = tid >> 5;
    int qt = 7 - (int)blockIdx.x;               // big tiles first
    int bh = blockIdx.y, b = bh >> 4, h = bh & 15;

    const float* Qg = qkv + ((size_t)(b * T_ + qt * 128)) * 3072 + h * 64;
    const float* Kg = qkv + (size_t)(b * T_) * 3072 + 1024 + h * 64;
    const float* Vg = qkv + (size_t)(b * T_) * 3072 + 2048 + h * 64;

    // load + split Q (128x64 fp32 -> [hi|lo|hi] bf16, pitch 200)
    #pragma unroll
    for (int i = 0; i < 8; ++i) {
        int idx = tid + i * 256;
        int r = idx >> 4, c4 = (idx & 15) * 4;
        float4 v = *(const float4*)(Qg + (size_t)r * 3072 + c4);
        float vv[4] = {v.x, v.y, v.z, v.w};
        #pragma unroll
        for (int j = 0; j < 4; ++j) {
            __nv_bfloat16 hi = __float2bfloat16(vv[j]);
            __nv_bfloat16 lo = __float2bfloat16(vv[j] - __bfloat162float(hi));
            Qs[r * 200 + c4 + j] = hi;
            Qs[r * 200 + 64 + c4 + j] = lo;
            Qs[r * 200 + 128 + c4 + j] = hi;
        }
    }

    float m0 = -INFINITY, m1 = -INFINITY, l0 = 0.f, l1 = 0.f;
    float O[8][4];
    #pragma unroll
    for (int j = 0; j < 8; ++j)
        #pragma unroll
        for (int e = 0; e < 4; ++e) O[j][e] = 0.f;

    float ps = p_scale[0];
    int g = lane >> 2, tg = lane & 3;
    int wr0 = wid * 16;
    int row_g0 = qt * 128 + wr0 + g;
    int nch = (qt * 128 + 128) >> 6;

    uint32_t aq_base = sQ + (wr0 + (lane & 15)) * 400 + (lane >> 4) * 16;
    uint32_t bk_base = sK + (((lane >> 3) & 2) * 4 + (lane & 7)) * 400 + ((lane >> 3) & 1) * 16;
    uint32_t v_roff = ((lane & 7) + ((lane >> 3) & 1) * 8) * 144 + ((lane >> 4) & 1) * 16;

    for (int ch = 0; ch < nch; ++ch) {
        int u0 = ch << 6;
        __syncthreads();
        // load + split K,V chunk (64x64 fp32 each)
        #pragma unroll
        for (int i = 0; i < 4; ++i) {
            int idx = tid + i * 256;
            int r = idx >> 4, c4 = (idx & 15) * 4;
            float4 kv = *(const float4*)(Kg + (size_t)(u0 + r) * 3072 + c4);
            float4 vv = *(const float4*)(Vg + (size_t)(u0 + r) * 3072 + c4);
            float ka[4] = {kv.x, kv.y, kv.z, kv.w};
            float va[4] = {vv.x, vv.y, vv.z, vv.w};
            #pragma unroll
            for (int j = 0; j < 4; ++j) {
                __nv_bfloat16 khi = __float2bfloat16(ka[j]);
                __nv_bfloat16 klo = __float2bfloat16(ka[j] - __bfloat162float(khi));
                Ks[r * 200 + c4 + j] = khi;
                Ks[r * 200 + 64 + c4 + j] = khi;
                Ks[r * 200 + 128 + c4 + j] = klo;
                __nv_bfloat16 vhi = __float2bfloat16(va[j]);
                __nv_bfloat16 vlo = __float2bfloat16(va[j] - __bfloat162float(vhi));
                Vh[r * 72 + c4 + j] = vhi;
                Vl[r * 72 + c4 + j] = vlo;
            }
        }
        __syncthreads();

        // S = Q @ K^T (K'=192 split)
        float c[8][4];
        #pragma unroll
        for (int j = 0; j < 8; ++j)
            #pragma unroll
            for (int e = 0; e < 4; ++e) c[j][e] = 0.f;
        #pragma unroll
        for (int ks = 0; ks < 12; ++ks) {
            uint32_t a[4];
            ldsm4(a, aq_base + ks * 32);
            #pragma unroll
            for (int jp = 0; jp < 4; ++jp) {
                uint32_t bb[4];
                ldsm4(bb, bk_base + jp * 16 * 400 + ks * 32);
                mma16816(c[jp * 2], a, bb);
                mma16816(c[jp * 2 + 1], a, bb + 2);
            }
        }

        // scale + p-adic bias + causal mask
        #pragma unroll
        for (int j = 0; j < 8; ++j) {
            int ub = u0 + j * 8 + tg * 2;
            #pragma unroll
            for (int e = 0; e < 4; ++e) {
                int row = row_g0 + (e >> 1) * 8;
                int u = ub + (e & 1);
                int d = row - u;
                if (d < 0) c[j][e] = -INFINITY;
                else {
                    float bias;
                    if (d == 0) bias = 1.f;
                    else {
                        int vp = __ffs(d) - 1;
                        vp = vp > 16 ? 16 : vp;
                        bias = (float)vp * (1.f / 16.f);
                    }
                    c[j][e] = c[j][e] * 0.125f + ps * bias;
                }
            }
        }

        // online softmax
        float mx0 = -INFINITY, mx1 = -INFINITY;
        #pragma unroll
        for (int j = 0; j < 8; ++j) {
            mx0 = fmaxf(mx0, fmaxf(c[j][0], c[j][1]));
            mx1 = fmaxf(mx1, fmaxf(c[j][2], c[j][3]));
        }
        mx0 = fmaxf(mx0, __shfl_xor_sync(0xffffffffu, mx0, 1));
        mx0 = fmaxf(mx0, __shfl_xor_sync(0xffffffffu, mx0, 2));
        mx1 = fmaxf(mx1, __shfl_xor_sync(0xffffffffu, mx1, 1));
        mx1 = fmaxf(mx1, __shfl_xor_sync(0xffffffffu, mx1, 2));
        float mn0 = fmaxf(m0, mx0), mn1 = fmaxf(m1, mx1);
        float al0 = __expf(m0 - mn0), al1 = __expf(m1 - mn1);
        float s0 = 0.f, s1 = 0.f;
        #pragma unroll
        for (int j = 0; j < 8; ++j) {
            c[j][0] = __expf(c[j][0] - mn0);
            c[j][1] = __expf(c[j][1] - mn0);
            c[j][2] = __expf(c[j][2] - mn1);
            c[j][3] = __expf(c[j][3] - mn1);
            s0 += c[j][0] + c[j][1];
            s1 += c[j][2] + c[j][3];
        }
        s0 += __shfl_xor_sync(0xffffffffu, s0, 1);
        s0 += __shfl_xor_sync(0xffffffffu, s0, 2);
        s1 += __shfl_xor_sync(0xffffffffu, s1, 1);
        s1 += __shfl_xor_sync(0xffffffffu, s1, 2);
        l0 = l0 * al0 + s0;
        l1 = l1 * al1 + s1;
        #pragma unroll
        for (int j = 0; j < 8; ++j) {
            O[j][0] *= al0; O[j][1] *= al0;
            O[j][2] *= al1; O[j][3] *= al1;
        }
        m0 = mn0; m1 = mn1;

        // O += P @ V  (P from regs: hi + lo split; V hi/lo from smem via trans ldsm)
        #pragma unroll
        for (int ms = 0; ms < 4; ++ms) {
            float ph[8], pl[8];
            #pragma unroll
            for (int e = 0; e < 4; ++e) {
                float v0 = c[2 * ms][e];
                float v1 = c[2 * ms + 1][e];
                __nv_bfloat16 h0 = __float2bfloat16(v0);
                __nv_bfloat16 h1 = __float2bfloat16(v1);
                ph[e] = __bfloat162float(h0);
                ph[4 + e] = __bfloat162float(h1);
                pl[e] = v0 - ph[e];
                pl[4 + e] = v1 - ph[4 + e];
            }
            uint32_t ah[4], al[4];
            ah[0] = packbf(ph[0], ph[1]); ah[1] = packbf(ph[2], ph[3]);
            ah[2] = packbf(ph[4], ph[5]); ah[3] = packbf(ph[6], ph[7]);
            al[0] = packbf(pl[0], pl[1]); al[1] = packbf(pl[2], pl[3]);
            al[2] = packbf(pl[4], pl[5]); al[3] = packbf(pl[6], pl[7]);
            uint32_t vaddr = v_roff + ms * 16 * 144;
            #pragma unroll
            for (int jp = 0; jp < 4; ++jp) {
                uint32_t vh[4], vl[4];
                ldsm4t(vh, sVh + vaddr + jp * 32);
                ldsm4t(vl, sVl + vaddr + jp * 32);
                mma16816(O[jp * 2],     ah, vh);
                mma16816(O[jp * 2 + 1], ah, vh + 2);
                mma16816(O[jp * 2],     al, vh);
                mma16816(O[jp * 2 + 1], al, vh + 2);
                mma16816(O[jp * 2],     ah, vl);
                mma16816(O[jp * 2 + 1], ah, vl + 2);
            }
        }
    }

    // epilogue: stage fp32 O/l in smem, then coalesced split write to exo
    __syncthreads();
    float* Of = (float*)sm_;        // [128][66]
    float i0 = 1.f / l0, i1 = 1.f / l1;
    #pragma unroll
    for (int j = 0; j < 8; ++j) {
        int cc = j * 8 + tg * 2;
        Of[(wr0 + g) * 66 + cc]     = O[j][0] * i0;
        Of[(wr0 + g) * 66 + cc + 1] = O[j][1] * i0;
        Of[(wr0 + g + 8) * 66 + cc]     = O[j][2] * i1;
        Of[(wr0 + g + 8) * 66 + cc + 1] = O[j][3] * i1;
    }
    __syncthreads();
    #pragma unroll
    for (int i = 0; i < 16; ++i) {
        int idx2 = tid + i * 256;              // 4096 bf162 units
        int r = idx2 >> 5, c2 = (idx2 & 31) * 2;
        float v0 = Of[r * 66 + c2], v1 = Of[r * 66 + c2 + 1];
        __nv_bfloat16 h0 = __float2bfloat16(v0);
        __nv_bfloat16 h1 = __float2bfloat16(v1);
        __nv_bfloat16 lo0 = __float2bfloat16(v0 - __bfloat162float(h0));
        __nv_bfloat16 lo1 = __float2bfloat16(v1 - __bfloat162float(h1));
        int tok = b * T_ + qt * 128 + r;
        size_t base = (size_t)tok * 3072 + h * 64 + c2;
        *(__nv_bfloat162*)(exo + base)        = __nv_bfloat162(h0, h1);
        *(__nv_bfloat162*)(exo + base + 1024) = __nv_bfloat162(lo0, lo1);
        *(__nv_bfloat162*)(exo + base + 2048) = __nv_bfloat162(h0, h1);
    }
}

// ---------------- reductions / prep ----------------
__device__ __forceinline__ float2 block_reduce2(float a, float b) {
    #pragma unroll
    for (int o = 16; o; o >>= 1) {
        a += __shfl_xor_sync(0xffffffffu, a, o);
        b += __shfl_xor_sync(0xffffffffu, b, o);
    }
    __shared__ float sa[8], sb2[8];
    int w = threadIdx.x >> 5, l = threadIdx.x & 31;
    int nw = (blockDim.x + 31) >> 5;
    if (l == 0) { sa[w] = a; sb2[w] = b; }
    __syncthreads();
    if (w == 0) {
        a = (l < nw) ? sa[l] : 0.f;
        b = (l < nw) ? sb2[l] : 0.f;
        #pragma unroll
        for (int o = 4; o; o >>= 1) {
            a += __shfl_xor_sync(0xffffffffu, a, o);
            b += __shfl_xor_sync(0xffffffffu, b, o);
        }
        if (l == 0) { sa[0] = a; sb2[0] = b; }
    }
    __syncthreads();
    return make_float2(sa[0], sb2[0]);
}

__global__ void reset_k() {
    if (threadIdx.x < 8) g_maxabs[threadIdx.x] = 0u;
}

__global__ __launch_bounds__(256) void absmax_all(const float* wq, const float* wk,
                                                  const float* wv, const float* wo,
                                                  const float* su, const float* sv,
                                                  const float* wup, const float* wdn) {
    int seg = blockIdx.x >> 8, blk = blockIdx.x & 255;
    const float* p; int n;
    switch (seg) {
        case 0: p = wq;  n = D_ * D_;   break;
        case 1: p = wk;  n = D_ * D_;   break;
        case 2: p = wv;  n = D_ * D_;   break;
        case 3: p = wo;  n = D_ * D_;   break;
        case 4: p = su;  n = S_ * S_;   break;
        case 5: p = sv;  n = S_ * S_;   break;
        case 6: p = wup; n = HID_ * D_; break;
        default: p = wdn; n = HID_ * D_; break;
    }
    float m = 0.f;
    for (int i = blk * 256 + threadIdx.x; i < n; i += 256 * 256)
        m = fmaxf(m, fabsf(p[i]));
    #pragma unroll
    for (int o = 16; o; o >>= 1) m = fmaxf(m, __shfl_xor_sync(0xffffffffu, m, o));
    __shared__ float sm[8];
    if ((threadIdx.x & 31) == 0) sm[threadIdx.x >> 5] = m;
    __syncthreads();
    if (threadIdx.x < 8) {
        m = sm[threadIdx.x];
        #pragma unroll
        for (int o = 4; o; o >>= 1) m = fmaxf(m, __shfl_xor_sync(0xffu, m, o));
        if (threadIdx.x == 0) atomicMax(&g_maxabs[seg], __float_as_uint(m));
    }
}

__global__ __launch_bounds__(256) void quant_k(const float* __restrict__ w, float* __restrict__ out,
                                               int n, int slot) {
    float scale = __uint_as_float(g_maxabs[slot]) / 31.0f + 1e-8f;
    int i = blockIdx.x * blockDim.x + threadIdx.x;
    if (i < n) {
        float q = rintf(w[i] / scale);
        q = fminf(fmaxf(q, -31.f), 31.f);
        out[i] = q * scale;
    }
}

// quantize + B-side split [hi|hi|lo], with destination row offset
__global__ __launch_bounds__(256) void quant_split_k(const float* __restrict__ w,
                                                     __nv_bfloat16* __restrict__ out,
                                                     int K, int slot, int total, int rowoff) {
    float scale = __uint_as_float(g_maxabs[slot]) / 31.0f + 1e-8f;
    int idx = blockIdx.x * blockDim.x + threadIdx.x;
    if (idx >= total) return;
    int n = idx / K, k = idx - n * K;
    float q = rintf(w[idx] / scale);
    q = fminf(fmaxf(q, -31.f), 31.f);
    float x = q * scale;
    __nv_bfloat16 h = __float2bfloat16(x);
    __nv_bfloat16 l = __float2bfloat16(x - __bfloat162float(h));
    size_t base = (size_t)(n + rowoff) * (3 * K) + k;
    out[base] = h; out[base + K] = h; out[base + 2 * K] = l;
}

// plain B-side split (already-quantized fp32 input)
__global__ __launch_bounds__(256) void split_b_k(const float* __restrict__ in,
                                                 __nv_bfloat16* __restrict__ out,
                                                 int K, int total, int rowoff) {
    int idx = blockIdx.x * blockDim.x + threadIdx.x;
    if (idx >= total) return;
    int n = idx / K, k = idx - n * K;
    float x = in[idx];
    __nv_bfloat16 h = __float2bfloat16(x);
    __nv_bfloat16 l = __float2bfloat16(x - __bfloat162float(h));
    size_t base = (size_t)(n + rowoff) * (3 * K) + k;
    out[base] = h; out[base + K] = h; out[base + 2 * K] = l;
}

// fw[h*64+s][k] = sum_j su[s][j] * w[h*64+j][k]
__global__ __launch_bounds__(256) void fuse_stalk_k(const float* __restrict__ su,
                                                    const float* __restrict__ w,
                                                    float* __restrict__ fw) {
    __shared__ float Ws[64][128];
    __shared__ float Ss[64][64];
    int h = blockIdx.y;
    int k0 = blockIdx.x * 128;
    int tid = threadIdx.x;
    #pragma unroll
    for (int it = 0; it < 8; ++it) {
        int chunk = tid + it * 256;
        int r = chunk >> 5, c4 = (chunk & 31) * 4;
        *(float4*)&Ws[r][c4] = *(const float4*)(w + (size_t)(h * 64 + r) * D_ + k0 + c4);
    }
    #pragma unroll
    for (int it = 0; it < 4; ++it) {
        int chunk = tid + it * 256;
        int r = chunk >> 4, c4 = (chunk & 15) * 4;
        *(float4*)&Ss[r][c4] = *(const float4*)(su + (size_t)r * 64 + c4);
    }
    __syncthreads();
    #pragma unroll 4
    for (int it = 0; it < 32; ++it) {
        int oidx = tid + it * 256;
        int s = oidx >> 7, kk = oidx & 127;
        float acc = 0.f;
        #pragma unroll
        for (int j = 0; j < 64; ++j) acc += Ss[s][j] * Ws[j][kk];
        fw[(size_t)(h * 64 + s) * D_ + k0 + kk] = acc;
    }
}

// layernorm(D) + A-side split [hi|lo|hi] direct to ex
__global__ __launch_bounds__(256) void ln_split_k(const float* __restrict__ x,
                                                  const float* __restrict__ g,
                                                  const float* __restrict__ bb,
                                                  __nv_bfloat16* __restrict__ out) {
    int row = blockIdx.x;
    const float* xr = x + (size_t)row * D_;
    int c = threadIdx.x * 4;
    float4 v = *(const float4*)(xr + c);
    float s = v.x + v.y + v.z + v.w;
    float sq = v.x * v.x + v.y * v.y + v.z * v.z + v.w * v.w;
    float2 r = block_reduce2(s, sq);
    float mu = r.x * (1.0f / D_);
    float var = r.y * (1.0f / D_) - mu * mu;
    float inv = rsqrtf(var + 1e-5f);
    float4 gg = *(const float4*)(g + c);
    float4 bv = *(const float4*)(bb + c);
    float o[4];
    o[0] = (v.x - mu) * inv * gg.x + bv.x;
    o[1] = (v.y - mu) * inv * gg.y + bv.y;
    o[2] = (v.z - mu) * inv * gg.z + bv.z;
    o[3] = (v.w - mu) * inv * gg.w + bv.w;
    size_t base = (size_t)row * 3072 + c;
    #pragma unroll
    for (int p2 = 0; p2 < 2; ++p2) {
        float a0 = o[p2 * 2], a1 = o[p2 * 2 + 1];
        __nv_bfloat16 h0 = __float2bfloat16(a0), h1 = __float2bfloat16(a1);
        __nv_bfloat16 l0 = __float2bfloat16(a0 - __bfloat162float(h0));
        __nv_bfloat16 l1 = __float2bfloat16(a1 - __bfloat162float(h1));
        *(__nv_bfloat162*)(out + base + p2 * 2)        = __nv_bfloat162(h0, h1);
        *(__nv_bfloat162*)(out + base + 1024 + p2 * 2) = __nv_bfloat162(l0, l1);
        *(__nv_bfloat162*)(out + base + 2048 + p2 * 2) = __nv_bfloat162(h0, h1);
    }
}

// SO(2) rotate + layernorm(HID) + SiLU + A-side split direct to e_h
__global__ __launch_bounds__(256) void rot_split_k(const float* __restrict__ hin,
                                                   const float* __restrict__ theta,
                                                   const float* __restrict__ g,
                                                   const float* __restrict__ bb,
                                                   __nv_bfloat16* __restrict__ out) {
    int row = blockIdx.x;
    const float* hrow = hin + (size_t)row * HID_;
    int tid = threadIdx.x;
    float r0[6], r1[6];
    float s = 0.f, sq = 0.f;
    #pragma unroll
    for (int i = 0; i < 6; ++i) {
        int p = tid + i * 256;
        float2 ab = *(const float2*)(hrow + 2 * p);
        float sn, cs;
        sincosf(theta[p], &sn, &cs);
        r0[i] = cs * ab.x - sn * ab.y;
        r1[i] = sn * ab.x + cs * ab.y;
        s += r0[i] + r1[i];
        sq += r0[i] * r0[i] + r1[i] * r1[i];
    }
    float2 r = block_reduce2(s, sq);
    float mu = r.x * (1.0f / HID_);
    float var = r.y * (1.0f / HID_) - mu * mu;
    float inv = rsqrtf(var + 1e-5f);
    size_t base = (size_t)row * (3 * HID_);
    #pragma unroll
    for (int i = 0; i < 6; ++i) {
        int p = tid + i * 256;
        int e0 = 2 * p, e1 = 2 * p + 1;
        float y0 = (r0[i] - mu) * inv * g[e0] + bb[e0];
        float y1 = (r1[i] - mu) * inv * g[e1] + bb[e1];
        y0 = y0 / (1.0f + __expf(-y0));
        y1 = y1 / (1.0f + __expf(-y1));
        __nv_bfloat16 h0 = __float2bfloat16(y0), h1 = __float2bfloat16(y1);
        __nv_bfloat16 l0 = __float2bfloat16(y0 - __bfloat162float(h0));
        __nv_bfloat16 l1 = __float2bfloat16(y1 - __bfloat162float(h1));
        *(__nv_bfloat162*)(out + base + e0)            = __nv_bfloat162(h0, h1);
        *(__nv_bfloat162*)(out + base + HID_ + e0)     = __nv_bfloat162(l0, l1);
        *(__nv_bfloat162*)(out + base + 2 * HID_ + e0) = __nv_bfloat162(h0, h1);
    }
}

// ---------------- host launcher ----------------
extern "C" void kernel_launch(void* const* d_in, const int* in_sizes, int n_in,
                              void* d_out, int out_size) {
    const float* x   = (const float*)d_in[0];
    const float* wq  = (const float*)d_in[1];
    const float* wk  = (const float*)d_in[2];
    const float* wv  = (const float*)d_in[3];
    const float* wo  = (const float*)d_in[4];
    const float* su  = (const float*)d_in[5];
    const float* sv  = (const float*)d_in[6];
    const float* ps  = (const float*)d_in[7];
    const float* n1g = (const float*)d_in[8];
    const float* n1b = (const float*)d_in[9];
    const float* n2g = (const float*)d_in[10];
    const float* n2b = (const float*)d_in[11];
    const float* wup = (const float*)d_in[12];
    const float* wdn = (const float*)d_in[13];
    const float* th  = (const float*)d_in[14];
    const float* mng = (const float*)d_in[15];
    const float* mnb = (const float*)d_in[16];
    float* out = (float*)d_out;

    float *qwq, *qwk, *qsu, *qsv, *fwq, *fwk, *hb;
    __nv_bfloat16 *ex, *eh, *eqkv, *ewo, *eup, *edn;
    cudaGetSymbolAddress((void**)&qwq, g_qwq);
    cudaGetSymbolAddress((void**)&qwk, g_qwk);
    cudaGetSymbolAddress((void**)&qsu, g_qsu);
    cudaGetSymbolAddress((void**)&qsv, g_qsv);
    cudaGetSymbolAddress((void**)&fwq, g_fwq);
    cudaGetSymbolAddress((void**)&fwk, g_fwk);
    cudaGetSymbolAddress((void**)&hb, g_h);
    cudaGetSymbolAddress((void**)&ex, e_x);
    cudaGetSymbolAddress((void**)&eh, e_h);
    cudaGetSymbolAddress((void**)&eqkv, e_qkv);
    cudaGetSymbolAddress((void**)&ewo, e_wo);
    cudaGetSymbolAddress((void**)&eup, e_up);
    cudaGetSymbolAddress((void**)&edn, e_dn);

    static bool attr_set = false;
    if (!attr_set) {
        cudaFuncSetAttribute(mm_hmma, cudaFuncAttributeMaxDynamicSharedMemorySize, MMX_SMEM);
        cudaFuncSetAttribute(flash_k, cudaFuncAttributeMaxDynamicSharedMemorySize, FL_SMEM);
        attr_set = true;
    }

    const int nDD = D_ * D_;
    const int nSS = S_ * S_;
    const int nUP = HID_ * D_;

    // weight prep
    reset_k<<<1, 32>>>();
    absmax_all<<<2048, 256>>>(wq, wk, wv, wo, su, sv, wup, wdn);
    quant_k<<<(nDD + 255) / 256, 256>>>(wq, qwq, nDD, 0);
    quant_k<<<(nDD + 255) / 256, 256>>>(wk, qwk, nDD, 1);
    quant_k<<<(nSS + 255) / 256, 256>>>(su, qsu, nSS, 4);
    quant_k<<<(nSS + 255) / 256, 256>>>(sv, qsv, nSS, 5);
    fuse_stalk_k<<<dim3(D_ / 128, H_), 256>>>(qsu, qwq, fwq);
    fuse_stalk_k<<<dim3(D_ / 128, H_), 256>>>(qsv, qwk, fwk);
    split_b_k<<<(nDD + 255) / 256, 256>>>(fwq, eqkv, D_, nDD, 0);
    split_b_k<<<(nDD + 255) / 256, 256>>>(fwk, eqkv, D_, nDD, 1024);
    quant_split_k<<<(nDD + 255) / 256, 256>>>(wv, eqkv, D_, 2, nDD, 2048);
    quant_split_k<<<(nDD + 255) / 256, 256>>>(wo, ewo, D_, 3, nDD, 0);
    quant_split_k<<<(nUP + 255) / 256, 256>>>(wup, eup, D_, 6, nUP, 0);
    quant_split_k<<<(nUP + 255) / 256, 256>>>(wdn, edn, HID_, 7, nUP, 0);

    // attention half
    ln_split_k<<<NTOK, 256>>>(x, n1g, n1b, ex);
    mm_hmma<<<dim3(24, 32), 256, MMX_SMEM>>>(ex, eqkv, nullptr, hb, NTOK, 3 * D_, 3 * D_);
    flash_k<<<dim3(8, 64), 256, FL_SMEM>>>(hb, ps, ex);
    mm_hmma<<<dim3(8, 32), 256, MMX_SMEM>>>(ex, ewo, x, out, NTOK, D_, 3 * D_);

    // MLP half
    ln_split_k<<<NTOK, 256>>>(out, n2g, n2b, ex);
    mm_hmma<<<dim3(24, 32), 256, MMX_SMEM>>>(ex, eup, nullptr, hb, NTOK, HID_, 3 * D_);
    rot_split_k<<<NTOK, 256>>>(hb, th, mng, mnb, eh);
    mm_hmma<<<dim3(8, 32), 256, MMX_SMEM>>>(eh, edn, out, out, NTOK, D_, 3 * HID_);
}